// round 7
// baseline (speedup 1.0000x reference)
#include <cuda_runtime.h>
#include <cuda_fp16.h>
#include <cstdint>

// Problem constants
#define T_TOK 8192
#define DDIM  4096
#define ODIM  4096
#define LMAX  8
#define RANK  16
#define KEXT  (LMAX * RANK)     // 128 extension columns
#define KTOT  (DDIM + KEXT)     // 4224

// ---------------------------------------------------------------------------
// Static device scratch (no allocations allowed)
// ---------------------------------------------------------------------------
__device__ __half g_xh[(size_t)T_TOK * DDIM];      // x  in fp16 (64 MB)
__device__ __half g_wh[(size_t)ODIM * DDIM];       // W  in fp16 (32 MB)
__device__ __half g_xe[(size_t)T_TOK * KEXT];      // S~ one-hot shrink (2 MB)
__device__ __half g_we[(size_t)ODIM * KEXT];       // B_cat (1 MB)
__device__ int    g_cnt[LMAX];                     // per-adapter token counts
__device__ int    g_tok[LMAX * T_TOK];             // per-adapter token lists

// ---------------------------------------------------------------------------
// PTX helpers (sm_80/90-era: legal on plain sm_103 target)
// ---------------------------------------------------------------------------
__device__ __forceinline__ uint32_t smem_u32(const void* p) {
    uint32_t a;
    asm("{ .reg .u64 t; cvta.to.shared.u64 t, %1; cvt.u32.u64 %0, t; }"
        : "=r"(a) : "l"(p));
    return a;
}
__device__ __forceinline__ void cp16(uint32_t d, const void* g) {
    asm volatile("cp.async.cg.shared.global [%0], [%1], 16;"
                 :: "r"(d), "l"(g) : "memory");
}
__device__ __forceinline__ void ldsm4(uint32_t* r, uint32_t a) {
    asm volatile("ldmatrix.sync.aligned.m8n8.x4.shared.b16 {%0,%1,%2,%3}, [%4];"
                 : "=r"(r[0]), "=r"(r[1]), "=r"(r[2]), "=r"(r[3]) : "r"(a));
}
__device__ __forceinline__ void mma_fp16(float* c, const uint32_t* a,
                                         uint32_t b0, uint32_t b1) {
    asm volatile(
        "mma.sync.aligned.m16n8k16.row.col.f32.f16.f16.f32 "
        "{%0,%1,%2,%3}, {%4,%5,%6,%7}, {%8,%9}, {%0,%1,%2,%3};"
        : "+f"(c[0]), "+f"(c[1]), "+f"(c[2]), "+f"(c[3])
        : "r"(a[0]), "r"(a[1]), "r"(a[2]), "r"(a[3]), "r"(b0), "r"(b1));
}

// ---------------------------------------------------------------------------
// Conversions
// ---------------------------------------------------------------------------
__global__ void conv_x(const float* __restrict__ in) {
    size_t n4 = (size_t)T_TOK * DDIM / 4;
    const float4* in4 = reinterpret_cast<const float4*>(in);
    for (size_t i = blockIdx.x * blockDim.x + threadIdx.x; i < n4;
         i += (size_t)gridDim.x * blockDim.x) {
        float4 v = in4[i];
        reinterpret_cast<__half2*>(g_xh)[i * 2]     = __floats2half2_rn(v.x, v.y);
        reinterpret_cast<__half2*>(g_xh)[i * 2 + 1] = __floats2half2_rn(v.z, v.w);
    }
}
__global__ void conv_w(const float* __restrict__ in) {
    size_t n4 = (size_t)ODIM * DDIM / 4;
    const float4* in4 = reinterpret_cast<const float4*>(in);
    for (size_t i = blockIdx.x * blockDim.x + threadIdx.x; i < n4;
         i += (size_t)gridDim.x * blockDim.x) {
        float4 v = in4[i];
        reinterpret_cast<__half2*>(g_wh)[i * 2]     = __floats2half2_rn(v.x, v.y);
        reinterpret_cast<__half2*>(g_wh)[i * 2 + 1] = __floats2half2_rn(v.z, v.w);
    }
}
// B_cat: g_we[o, l*16+r] = lora_b[l, o, r]; also zeroes g_cnt (runs before lists)
__global__ void conv_we(const float* __restrict__ lb) {
    const int i = blockIdx.x * blockDim.x + threadIdx.x;   // over ODIM*LMAX
    if (blockIdx.x == 0 && threadIdx.x < LMAX) g_cnt[threadIdx.x] = 0;
    if (i >= ODIM * LMAX) return;
    const int o = i >> 3;
    const int l = i & 7;
    const float4* src = reinterpret_cast<const float4*>(lb + ((size_t)l * ODIM + o) * RANK);
    __half2 h[8];
#pragma unroll
    for (int q = 0; q < 4; q++) {
        float4 v = src[q];
        h[q * 2]     = __floats2half2_rn(v.x, v.y);
        h[q * 2 + 1] = __floats2half2_rn(v.z, v.w);
    }
    __half2* dst = reinterpret_cast<__half2*>(g_we + (size_t)o * KEXT + l * RANK);
    *reinterpret_cast<uint4*>(dst)     = *reinterpret_cast<uint4*>(h);
    *reinterpret_cast<uint4*>(dst + 4) = *reinterpret_cast<uint4*>(h + 4);
}

__global__ void build_lists(const int* __restrict__ idx) {
    const int t = blockIdx.x * blockDim.x + threadIdx.x;
    if (t < T_TOK) {
        const int l = idx[t];
        const int p = atomicAdd(&g_cnt[l], 1);
        g_tok[l * T_TOK + p] = t;
    }
}

// ---------------------------------------------------------------------------
// Adapter-grouped LoRA shrink -> one-hot fp16 rows g_xe[t, :].
// Block = (adapter l, group of 128 tokens). A_l chunk staged in SMEM (fp32).
// Thread (ti, ds): token ti, d-slices of 8: d = 16j + 8*ds.
// ---------------------------------------------------------------------------
__global__ __launch_bounds__(256, 1)
void shrink_grouped(const float* __restrict__ la) {
    const int l = blockIdx.x;
    const int start = blockIdx.y * 128;
    const int cnt = g_cnt[l];
    if (start >= cnt) return;
    const int tid = threadIdx.x;
    const int ti = tid >> 1;
    const int ds = tid & 1;

    __shared__ float Asm[RANK][512];
    __shared__ int toks[128];
    if (tid < 128)
        toks[tid] = (start + tid < cnt) ? g_tok[l * T_TOK + start + tid] : -1;
    __syncthreads();
    const int t = toks[ti];

    float acc[RANK];
#pragma unroll
    for (int r = 0; r < RANK; r++) acc[r] = 0.f;

    for (int ch = 0; ch < DDIM / 512; ch++) {
        const float* Ab = la + (size_t)l * RANK * DDIM + ch * 512;
#pragma unroll
        for (int it = 0; it < 8; it++) {              // 2048 float4 loads
            const int i = it * 256 + tid;
            const int r = i >> 7;
            const int c4 = i & 127;
            reinterpret_cast<float4*>(&Asm[r][0])[c4] =
                reinterpret_cast<const float4*>(Ab + (size_t)r * DDIM)[c4];
        }
        __syncthreads();
        if (t >= 0) {
            const __half2* xr = reinterpret_cast<const __half2*>(
                g_xh + (size_t)t * DDIM + ch * 512);
#pragma unroll
            for (int j = 0; j < 32; j++) {
                const int d = j * 16 + ds * 8;
                float2 x01 = __half22float2(xr[(d >> 1) + 0]);
                float2 x23 = __half22float2(xr[(d >> 1) + 1]);
                float2 x45 = __half22float2(xr[(d >> 1) + 2]);
                float2 x67 = __half22float2(xr[(d >> 1) + 3]);
#pragma unroll
                for (int r = 0; r < RANK; r++) {
                    float4 a0 = *reinterpret_cast<const float4*>(&Asm[r][d]);
                    float4 a1 = *reinterpret_cast<const float4*>(&Asm[r][d + 4]);
                    acc[r] += x01.x * a0.x + x01.y * a0.y + x23.x * a0.z + x23.y * a0.w +
                              x45.x * a1.x + x45.y * a1.y + x67.x * a1.z + x67.y * a1.w;
                }
            }
        }
        __syncthreads();
    }

    // Reduce across the 2 d-slice threads (adjacent lanes)
#pragma unroll
    for (int r = 0; r < RANK; r++)
        acc[r] += __shfl_xor_sync(0xffffffffu, acc[r], 1);

    if (ds == 0 && t >= 0) {
        __half2* row = reinterpret_cast<__half2*>(g_xe + (size_t)t * KEXT);
        const int c0 = l * (RANK / 2);
#pragma unroll
        for (int c = 0; c < KEXT / 2; c++) {
            __half2 v = __floats2half2_rn(0.f, 0.f);
            if (c >= c0 && c < c0 + RANK / 2)
                v = __floats2half2_rn(acc[(c - c0) * 2], acc[(c - c0) * 2 + 1]);
            row[c] = v;
        }
    }
}

// ---------------------------------------------------------------------------
// Fused GEMM: out = [x | S~] @ [W | B_cat]^T   (fp16 mma.sync, fp32 accum)
// 128x128 CTA tile, BK=64, 3-stage cp.async pipeline (96 KB SMEM),
// 4 warps (each 64x64), 2 CTAs/SM for overlapping barrier domains.
// Rows 128 B = 8 x 16B chunks, swizzle phys_chunk = c ^ (row & 7).
// ---------------------------------------------------------------------------
#define BKC     64
#define NCHUNKC (KTOT / BKC)                  // 66
#define A_TILEB (128 * 128)
#define B_TILEB (128 * 128)
#define STAGEB  (A_TILEB + B_TILEB)           // 32 KB
#define STAGES  3
#define GEMM_SMEM (STAGES * STAGEB)           // 96 KB

__global__ __launch_bounds__(128, 2)
void gemm_mma(float* __restrict__ C) {
    extern __shared__ char smem[];
    const uint32_t sb = smem_u32(smem);
    const int tid  = threadIdx.x;
    const int wid  = tid >> 5;
    const int lane = tid & 31;

    // Rasterize: GROUP_M=8 so a wave's working set stays L2-resident
    const int bid = blockIdx.x;
    const int TN = ODIM / 128;                 // 32
    const int GRP = 8;
    const int per = GRP * TN;                  // 256
    const int m_t = (bid / per) * GRP + (bid % per) % GRP;
    const int n_t = (bid % per) / GRP;
    const int bm = m_t * 128;
    const int bn = n_t * 128;

    const int warp_m = wid & 1;   // 2 x 64 rows
    const int warp_n = wid >> 1;  // 2 x 64 cols

    // -------- async loader: 16 x cp16 per thread per chunk --------
    auto issue_chunk = [&](int chunk, int stage) {
        const int k0 = chunk * BKC;
        const bool ext = (k0 >= DDIM);
        const __half* asrc = ext ? g_xe : g_xh;
        const __half* bsrc = ext ? g_we : g_wh;
        const size_t astr = ext ? KEXT : DDIM;
        const int ak = ext ? (k0 - DDIM) : k0;
        const uint32_t sbase = sb + (uint32_t)stage * STAGEB;
#pragma unroll
        for (int rep = 0; rep < 8; rep++) {            // A: 1024 cp16
            const int idx = rep * 128 + tid;
            const int r = idx >> 3;
            const int c = idx & 7;
            const void* g = asrc + (size_t)(bm + r) * astr + ak + c * 8;
            cp16(sbase + r * 128 + ((c ^ (r & 7)) << 4), g);
        }
#pragma unroll
        for (int rep = 0; rep < 8; rep++) {            // B: 1024 cp16
            const int idx = rep * 128 + tid;
            const int r = idx >> 3;
            const int c = idx & 7;
            const void* g = bsrc + (size_t)(bn + r) * astr + ak + c * 8;
            cp16(sbase + A_TILEB + r * 128 + ((c ^ (r & 7)) << 4), g);
        }
        asm volatile("cp.async.commit_group;" ::: "memory");
    };

    float acc[4][8][4];
#pragma unroll
    for (int i = 0; i < 4; i++)
#pragma unroll
        for (int j = 0; j < 8; j++)
#pragma unroll
            for (int q = 0; q < 4; q++) acc[i][j][q] = 0.f;

#pragma unroll
    for (int s = 0; s < STAGES - 1; s++) issue_chunk(s, s);

    const int a_r = lane & 15;
    const int a_h = lane >> 4;
    const int b_r = (lane & 7) + ((lane >> 4) << 3);
    const int b_h = (lane >> 3) & 1;

    for (int i = 0; i < NCHUNKC; i++) {
        const int stage = i % STAGES;
        asm volatile("cp.async.wait_group %0;" :: "n"(STAGES - 2) : "memory");
        __syncthreads();
        if (i + STAGES - 1 < NCHUNKC)
            issue_chunk(i + STAGES - 1, (i + STAGES - 1) % STAGES);

        const uint32_t Ab = sb + (uint32_t)stage * STAGEB;
        const uint32_t Bb = Ab + A_TILEB;

#pragma unroll
        for (int ks = 0; ks < 4; ks++) {
            uint32_t af[4][4], bf[4][4];
#pragma unroll
            for (int mt = 0; mt < 4; mt++) {
                const int row = warp_m * 64 + mt * 16 + a_r;
                const int cl = ks * 2 + a_h;
                ldsm4(af[mt], Ab + row * 128 + ((cl ^ (row & 7)) << 4));
            }
#pragma unroll
            for (int p = 0; p < 4; p++) {
                const int row = warp_n * 64 + p * 16 + b_r;
                const int cl = ks * 2 + b_h;
                ldsm4(bf[p], Bb + row * 128 + ((cl ^ (row & 7)) << 4));
            }
#pragma unroll
            for (int mt = 0; mt < 4; mt++)
#pragma unroll
                for (int nt = 0; nt < 8; nt++)
                    mma_fp16(acc[mt][nt], af[mt],
                             bf[nt >> 1][(nt & 1) * 2], bf[nt >> 1][(nt & 1) * 2 + 1]);
        }
    }

    const int er = lane >> 2;
    const int ec = (lane & 3) * 2;
#pragma unroll
    for (int mt = 0; mt < 4; mt++) {
#pragma unroll
        for (int nt = 0; nt < 8; nt++) {
            float* base = C + (size_t)(bm + warp_m * 64 + mt * 16 + er) * ODIM +
                          bn + warp_n * 64 + nt * 8 + ec;
            *reinterpret_cast<float2*>(base) =
                make_float2(acc[mt][nt][0], acc[mt][nt][1]);
            *reinterpret_cast<float2*>(base + 8 * ODIM) =
                make_float2(acc[mt][nt][2], acc[mt][nt][3]);
        }
    }
}

// ---------------------------------------------------------------------------
// Launch: inputs order: x, weight, lora_a, lora_b, token_lora_idx
// ---------------------------------------------------------------------------
extern "C" void kernel_launch(void* const* d_in, const int* in_sizes, int n_in,
                              void* d_out, int out_size) {
    const float* x   = (const float*)d_in[0];
    const float* w   = (const float*)d_in[1];
    const float* la  = (const float*)d_in[2];
    const float* lb  = (const float*)d_in[3];
    const int*   idx = (const int*)d_in[4];
    float* out = (float*)d_out;

    cudaFuncSetAttribute(gemm_mma, cudaFuncAttributeMaxDynamicSharedMemorySize,
                         GEMM_SMEM);

    conv_x<<<1024, 256>>>(x);
    conv_w<<<1024, 256>>>(w);
    conv_we<<<(ODIM * LMAX + 255) / 256, 256>>>(lb);    // also zeroes g_cnt

    build_lists<<<T_TOK / 256, 256>>>(idx);
    shrink_grouped<<<dim3(LMAX, T_TOK / 128), 256>>>(la);

    gemm_mma<<<(T_TOK / 128) * (ODIM / 128), 128, GEMM_SMEM>>>(out);
}

// round 8
// speedup vs baseline: 1.4984x; 1.4984x over previous
#include <cuda_runtime.h>
#include <cuda_fp16.h>
#include <cstdint>

// Problem constants
#define T_TOK 8192
#define DDIM  4096
#define ODIM  4096
#define LMAX  8
#define RANK  16
#define KEXT  (LMAX * RANK)     // 128 extension columns
#define KTOT  (DDIM + KEXT)     // 4224

// ---------------------------------------------------------------------------
// Static device scratch (no allocations allowed)
// ---------------------------------------------------------------------------
__device__ __half g_xh[(size_t)T_TOK * DDIM];      // x  in fp16 (64 MB)
__device__ __half g_wh[(size_t)ODIM * DDIM];       // W  in fp16 (32 MB)
__device__ __half g_xe[(size_t)T_TOK * KEXT];      // S~ one-hot shrink (2 MB)
__device__ __half g_we[(size_t)ODIM * KEXT];       // B_cat (1 MB)
__device__ int    g_cnt[LMAX];                     // per-adapter token counts
__device__ int    g_tok[LMAX * T_TOK];             // per-adapter token lists

// ---------------------------------------------------------------------------
// PTX helpers (sm_80/90-era: legal on plain sm_103 target)
// ---------------------------------------------------------------------------
__device__ __forceinline__ uint32_t smem_u32(const void* p) {
    uint32_t a;
    asm("{ .reg .u64 t; cvta.to.shared.u64 t, %1; cvt.u32.u64 %0, t; }"
        : "=r"(a) : "l"(p));
    return a;
}
__device__ __forceinline__ void cp16(uint32_t d, const void* g) {
    asm volatile("cp.async.cg.shared.global [%0], [%1], 16;"
                 :: "r"(d), "l"(g) : "memory");
}
__device__ __forceinline__ void ldsm4(uint32_t* r, uint32_t a) {
    asm volatile("ldmatrix.sync.aligned.m8n8.x4.shared.b16 {%0,%1,%2,%3}, [%4];"
                 : "=r"(r[0]), "=r"(r[1]), "=r"(r[2]), "=r"(r[3]) : "r"(a));
}
__device__ __forceinline__ void mma_fp16(float* c, const uint32_t* a,
                                         uint32_t b0, uint32_t b1) {
    asm volatile(
        "mma.sync.aligned.m16n8k16.row.col.f32.f16.f16.f32 "
        "{%0,%1,%2,%3}, {%4,%5,%6,%7}, {%8,%9}, {%0,%1,%2,%3};"
        : "+f"(c[0]), "+f"(c[1]), "+f"(c[2]), "+f"(c[3])
        : "r"(a[0]), "r"(a[1]), "r"(a[2]), "r"(a[3]), "r"(b0), "r"(b1));
}
// Packed fp32x2 FMA (Blackwell): d += a*b elementwise on 2 lanes
__device__ __forceinline__ void fma2(unsigned long long& d,
                                     unsigned long long a,
                                     unsigned long long b) {
    asm("fma.rn.f32x2 %0, %1, %2, %3;" : "=l"(d) : "l"(a), "l"(b), "l"(d));
}
__device__ __forceinline__ unsigned long long pack2(float x, float y) {
    unsigned long long r;
    asm("mov.b64 %0, {%1, %2};" : "=l"(r) : "r"(__float_as_uint(x)), "r"(__float_as_uint(y)));
    return r;
}
__device__ __forceinline__ float2 unpack2(unsigned long long v) {
    uint32_t lo, hi;
    asm("mov.b64 {%0, %1}, %2;" : "=r"(lo), "=r"(hi) : "l"(v));
    return make_float2(__uint_as_float(lo), __uint_as_float(hi));
}

// ---------------------------------------------------------------------------
// Conversions
// ---------------------------------------------------------------------------
__global__ void conv_x(const float* __restrict__ in) {
    size_t n4 = (size_t)T_TOK * DDIM / 4;
    const float4* in4 = reinterpret_cast<const float4*>(in);
    for (size_t i = blockIdx.x * blockDim.x + threadIdx.x; i < n4;
         i += (size_t)gridDim.x * blockDim.x) {
        float4 v = in4[i];
        reinterpret_cast<__half2*>(g_xh)[i * 2]     = __floats2half2_rn(v.x, v.y);
        reinterpret_cast<__half2*>(g_xh)[i * 2 + 1] = __floats2half2_rn(v.z, v.w);
    }
}
__global__ void conv_w(const float* __restrict__ in) {
    size_t n4 = (size_t)ODIM * DDIM / 4;
    const float4* in4 = reinterpret_cast<const float4*>(in);
    for (size_t i = blockIdx.x * blockDim.x + threadIdx.x; i < n4;
         i += (size_t)gridDim.x * blockDim.x) {
        float4 v = in4[i];
        reinterpret_cast<__half2*>(g_wh)[i * 2]     = __floats2half2_rn(v.x, v.y);
        reinterpret_cast<__half2*>(g_wh)[i * 2 + 1] = __floats2half2_rn(v.z, v.w);
    }
}
// B_cat: g_we[o, l*16+r] = lora_b[l, o, r]; also zeroes g_cnt (runs before lists)
__global__ void conv_we(const float* __restrict__ lb) {
    const int i = blockIdx.x * blockDim.x + threadIdx.x;   // over ODIM*LMAX
    if (blockIdx.x == 0 && threadIdx.x < LMAX) g_cnt[threadIdx.x] = 0;
    if (i >= ODIM * LMAX) return;
    const int o = i >> 3;
    const int l = i & 7;
    const float4* src = reinterpret_cast<const float4*>(lb + ((size_t)l * ODIM + o) * RANK);
    __half2 h[8];
#pragma unroll
    for (int q = 0; q < 4; q++) {
        float4 v = src[q];
        h[q * 2]     = __floats2half2_rn(v.x, v.y);
        h[q * 2 + 1] = __floats2half2_rn(v.z, v.w);
    }
    __half2* dst = reinterpret_cast<__half2*>(g_we + (size_t)o * KEXT + l * RANK);
    *reinterpret_cast<uint4*>(dst)     = *reinterpret_cast<uint4*>(h);
    *reinterpret_cast<uint4*>(dst + 4) = *reinterpret_cast<uint4*>(h + 4);
}

__global__ void build_lists(const int* __restrict__ idx) {
    const int t = blockIdx.x * blockDim.x + threadIdx.x;
    if (t < T_TOK) {
        const int l = idx[t];
        const int p = atomicAdd(&g_cnt[l], 1);
        g_tok[l * T_TOK + p] = t;
    }
}

// ---------------------------------------------------------------------------
// Adapter-grouped LoRA shrink -> one-hot fp16 rows g_xe[t, :].
// Block = (adapter l, group of 64 tokens). A_l chunk (fp32) staged in SMEM.
// Thread (ti, ds): token ti (0..63), d-slice ds (0..3): d = 16j + 4ds.
// fp32 math via packed fma.f32x2; x read directly from fp32 input (no CVTs).
// ---------------------------------------------------------------------------
__global__ __launch_bounds__(256, 1)
void shrink_grouped(const float* __restrict__ x, const float* __restrict__ la) {
    const int l = blockIdx.x;
    const int start = blockIdx.y * 64;
    const int cnt = g_cnt[l];
    if (start >= cnt) return;
    const int tid = threadIdx.x;
    const int ti = tid >> 2;
    const int ds = tid & 3;

    __shared__ float Asm[RANK][512];
    __shared__ int toks[64];
    if (tid < 64)
        toks[tid] = (start + tid < cnt) ? g_tok[l * T_TOK + start + tid] : -1;
    __syncthreads();
    const int t = toks[ti];

    unsigned long long acc2[RANK];
#pragma unroll
    for (int r = 0; r < RANK; r++) acc2[r] = 0ull;

    for (int ch = 0; ch < DDIM / 512; ch++) {
        const float* Ab = la + (size_t)l * RANK * DDIM + ch * 512;
#pragma unroll
        for (int it = 0; it < 8; it++) {              // 2048 float4 loads
            const int i = it * 256 + tid;
            const int r = i >> 7;
            const int c4 = i & 127;
            reinterpret_cast<float4*>(&Asm[r][0])[c4] =
                reinterpret_cast<const float4*>(Ab + (size_t)r * DDIM)[c4];
        }
        __syncthreads();
        if (t >= 0) {
            const float* xr = x + (size_t)t * DDIM + ch * 512;
#pragma unroll
            for (int j = 0; j < 32; j++) {
                const int d = j * 16 + ds * 4;
                float4 xv = *reinterpret_cast<const float4*>(xr + d);
                const unsigned long long x01 = pack2(xv.x, xv.y);
                const unsigned long long x23 = pack2(xv.z, xv.w);
#pragma unroll
                for (int r = 0; r < RANK; r++) {
                    const unsigned long long* ap =
                        reinterpret_cast<const unsigned long long*>(&Asm[r][d]);
                    fma2(acc2[r], x01, ap[0]);
                    fma2(acc2[r], x23, ap[1]);
                }
            }
        }
        __syncthreads();
    }

    // Collapse f32x2 lanes, then reduce across the 4 d-slice threads
    float acc[RANK];
#pragma unroll
    for (int r = 0; r < RANK; r++) {
        float2 v = unpack2(acc2[r]);
        acc[r] = v.x + v.y;
        acc[r] += __shfl_xor_sync(0xffffffffu, acc[r], 1);
        acc[r] += __shfl_xor_sync(0xffffffffu, acc[r], 2);
    }

    if (ds == 0 && t >= 0) {
        __half2* row = reinterpret_cast<__half2*>(g_xe + (size_t)t * KEXT);
        const int c0 = l * (RANK / 2);
#pragma unroll
        for (int c = 0; c < KEXT / 2; c++) {
            __half2 v = __floats2half2_rn(0.f, 0.f);
            if (c >= c0 && c < c0 + RANK / 2)
                v = __floats2half2_rn(acc[(c - c0) * 2], acc[(c - c0) * 2 + 1]);
            row[c] = v;
        }
    }
}

// ---------------------------------------------------------------------------
// Fused GEMM: out = [x | S~] @ [W | B_cat]^T   (fp16 mma.sync, fp32 accum)
// 128x256 CTA tile, BK=64, 4-stage cp.async pipeline (192 KB SMEM), 8 warps.
// Rows 128 B = 8 x 16B chunks, swizzle phys_chunk = c ^ (row & 7).  (R6 proven)
// ---------------------------------------------------------------------------
#define BKC     64
#define NCHUNKC (KTOT / BKC)                  // 66
#define A_TILEB (128 * 128)
#define B_TILEB (256 * 128)
#define STAGEB  (A_TILEB + B_TILEB)           // 48 KB
#define STAGES  4
#define GEMM_SMEM (STAGES * STAGEB)           // 192 KB

__global__ __launch_bounds__(256, 1)
void gemm_mma(float* __restrict__ C) {
    extern __shared__ char smem[];
    const uint32_t sb = smem_u32(smem);
    const int tid  = threadIdx.x;
    const int wid  = tid >> 5;
    const int lane = tid & 31;

    const int bid = blockIdx.x;
    const int TN = ODIM / 256;                 // 16
    const int GRP = 8;
    const int per = GRP * TN;                  // 128
    const int m_t = (bid / per) * GRP + (bid % per) % GRP;
    const int n_t = (bid % per) / GRP;
    const int bm = m_t * 128;
    const int bn = n_t * 256;

    const int warp_m = wid & 1;
    const int warp_n = wid >> 1;

    auto issue_chunk = [&](int chunk, int stage) {
        const int k0 = chunk * BKC;
        const bool ext = (k0 >= DDIM);
        const __half* asrc = ext ? g_xe : g_xh;
        const __half* bsrc = ext ? g_we : g_wh;
        const size_t astr = ext ? KEXT : DDIM;
        const int ak = ext ? (k0 - DDIM) : k0;
        const uint32_t sbase = sb + (uint32_t)stage * STAGEB;
#pragma unroll
        for (int rep = 0; rep < 4; rep++) {            // A: 1024 cp16
            const int idx = rep * 256 + tid;
            const int r = idx >> 3;
            const int c = idx & 7;
            const void* g = asrc + (size_t)(bm + r) * astr + ak + c * 8;
            cp16(sbase + r * 128 + ((c ^ (r & 7)) << 4), g);
        }
#pragma unroll
        for (int rep = 0; rep < 8; rep++) {            // B: 2048 cp16
            const int idx = rep * 256 + tid;
            const int r = idx >> 3;
            const int c = idx & 7;
            const void* g = bsrc + (size_t)(bn + r) * astr + ak + c * 8;
            cp16(sbase + A_TILEB + r * 128 + ((c ^ (r & 7)) << 4), g);
        }
        asm volatile("cp.async.commit_group;" ::: "memory");
    };

    float acc[4][8][4];
#pragma unroll
    for (int i = 0; i < 4; i++)
#pragma unroll
        for (int j = 0; j < 8; j++)
#pragma unroll
            for (int q = 0; q < 4; q++) acc[i][j][q] = 0.f;

#pragma unroll
    for (int s = 0; s < STAGES - 1; s++) issue_chunk(s, s);

    const int a_r = lane & 15;
    const int a_h = lane >> 4;
    const int b_r = (lane & 7) + ((lane >> 4) << 3);
    const int b_h = (lane >> 3) & 1;

    for (int i = 0; i < NCHUNKC; i++) {
        const int stage = i % STAGES;
        asm volatile("cp.async.wait_group %0;" :: "n"(STAGES - 2) : "memory");
        __syncthreads();
        if (i + STAGES - 1 < NCHUNKC)
            issue_chunk(i + STAGES - 1, (i + STAGES - 1) % STAGES);

        const uint32_t Ab = sb + (uint32_t)stage * STAGEB;
        const uint32_t Bb = Ab + A_TILEB;

#pragma unroll
        for (int ks = 0; ks < 4; ks++) {
            uint32_t af[4][4], bf[4][4];
#pragma unroll
            for (int mt = 0; mt < 4; mt++) {
                const int row = warp_m * 64 + mt * 16 + a_r;
                const int cl = ks * 2 + a_h;
                ldsm4(af[mt], Ab + row * 128 + ((cl ^ (row & 7)) << 4));
            }
#pragma unroll
            for (int p = 0; p < 4; p++) {
                const int row = warp_n * 64 + p * 16 + b_r;
                const int cl = ks * 2 + b_h;
                ldsm4(bf[p], Bb + row * 128 + ((cl ^ (row & 7)) << 4));
            }
#pragma unroll
            for (int mt = 0; mt < 4; mt++)
#pragma unroll
                for (int nt = 0; nt < 8; nt++)
                    mma_fp16(acc[mt][nt], af[mt],
                             bf[nt >> 1][(nt & 1) * 2], bf[nt >> 1][(nt & 1) * 2 + 1]);
        }
    }

    const int er = lane >> 2;
    const int ec = (lane & 3) * 2;
#pragma unroll
    for (int mt = 0; mt < 4; mt++) {
#pragma unroll
        for (int nt = 0; nt < 8; nt++) {
            float* base = C + (size_t)(bm + warp_m * 64 + mt * 16 + er) * ODIM +
                          bn + warp_n * 64 + nt * 8 + ec;
            *reinterpret_cast<float2*>(base) =
                make_float2(acc[mt][nt][0], acc[mt][nt][1]);
            *reinterpret_cast<float2*>(base + 8 * ODIM) =
                make_float2(acc[mt][nt][2], acc[mt][nt][3]);
        }
    }
}

// ---------------------------------------------------------------------------
// Launch: inputs order: x, weight, lora_a, lora_b, token_lora_idx
// ---------------------------------------------------------------------------
extern "C" void kernel_launch(void* const* d_in, const int* in_sizes, int n_in,
                              void* d_out, int out_size) {
    const float* x   = (const float*)d_in[0];
    const float* w   = (const float*)d_in[1];
    const float* la  = (const float*)d_in[2];
    const float* lb  = (const float*)d_in[3];
    const int*   idx = (const int*)d_in[4];
    float* out = (float*)d_out;

    cudaFuncSetAttribute(gemm_mma, cudaFuncAttributeMaxDynamicSharedMemorySize,
                         GEMM_SMEM);

    conv_x<<<1024, 256>>>(x);
    conv_w<<<1024, 256>>>(w);
    conv_we<<<(ODIM * LMAX + 255) / 256, 256>>>(lb);    // also zeroes g_cnt

    build_lists<<<T_TOK / 256, 256>>>(idx);
    shrink_grouped<<<dim3(LMAX, T_TOK / 64), 256>>>(x, la);

    gemm_mma<<<(T_TOK / 128) * (ODIM / 256), 256, GEMM_SMEM>>>(out);
}

// round 9
// speedup vs baseline: 1.6322x; 1.0893x over previous
#include <cuda_runtime.h>
#include <cuda_fp16.h>
#include <cstdint>

// Problem constants
#define T_TOK 8192
#define DDIM  4096
#define ODIM  4096
#define LMAX  8
#define RANK  16
#define KEXT  (LMAX * RANK)     // 128 extension columns
#define KTOT  (DDIM + KEXT)     // 4224

// ---------------------------------------------------------------------------
// Static device scratch (no allocations allowed)
// ---------------------------------------------------------------------------
__device__ __half g_xh[(size_t)T_TOK * DDIM];      // x  in fp16 (64 MB) - written by shrink
__device__ __half g_wh[(size_t)ODIM * DDIM];       // W  in fp16 (32 MB)
__device__ __half g_xe[(size_t)T_TOK * KEXT];      // S~ one-hot shrink (2 MB)
__device__ __half g_we[(size_t)ODIM * KEXT];       // B_cat (1 MB)
__device__ int    g_cnt[LMAX];                     // per-adapter token counts
__device__ int    g_tok[LMAX * T_TOK];             // per-adapter token lists

// ---------------------------------------------------------------------------
// PTX helpers (sm_80/90-era: legal on plain sm_103 target)
// ---------------------------------------------------------------------------
__device__ __forceinline__ uint32_t smem_u32(const void* p) {
    uint32_t a;
    asm("{ .reg .u64 t; cvta.to.shared.u64 t, %1; cvt.u32.u64 %0, t; }"
        : "=r"(a) : "l"(p));
    return a;
}
__device__ __forceinline__ void cp16(uint32_t d, const void* g) {
    asm volatile("cp.async.cg.shared.global [%0], [%1], 16;"
                 :: "r"(d), "l"(g) : "memory");
}
__device__ __forceinline__ void ldsm4(uint32_t* r, uint32_t a) {
    asm volatile("ldmatrix.sync.aligned.m8n8.x4.shared.b16 {%0,%1,%2,%3}, [%4];"
                 : "=r"(r[0]), "=r"(r[1]), "=r"(r[2]), "=r"(r[3]) : "r"(a));
}
__device__ __forceinline__ void mma_fp16(float* c, const uint32_t* a,
                                         uint32_t b0, uint32_t b1) {
    asm volatile(
        "mma.sync.aligned.m16n8k16.row.col.f32.f16.f16.f32 "
        "{%0,%1,%2,%3}, {%4,%5,%6,%7}, {%8,%9}, {%0,%1,%2,%3};"
        : "+f"(c[0]), "+f"(c[1]), "+f"(c[2]), "+f"(c[3])
        : "r"(a[0]), "r"(a[1]), "r"(a[2]), "r"(a[3]), "r"(b0), "r"(b1));
}
// Packed fp32x2 FMA (Blackwell)
__device__ __forceinline__ void fma2(unsigned long long& d,
                                     unsigned long long a,
                                     unsigned long long b) {
    asm("fma.rn.f32x2 %0, %1, %2, %3;" : "=l"(d) : "l"(a), "l"(b), "l"(d));
}
__device__ __forceinline__ unsigned long long pack2(float x, float y) {
    unsigned long long r;
    asm("mov.b64 %0, {%1, %2};" : "=l"(r) : "r"(__float_as_uint(x)), "r"(__float_as_uint(y)));
    return r;
}
__device__ __forceinline__ float2 unpack2(unsigned long long v) {
    uint32_t lo, hi;
    asm("mov.b64 {%0, %1}, %2;" : "=r"(lo), "=r"(hi) : "l"(v));
    return make_float2(__uint_as_float(lo), __uint_as_float(hi));
}

// ---------------------------------------------------------------------------
// Conversions (W path only; x is converted inside shrink)
// ---------------------------------------------------------------------------
__global__ void conv_w(const float* __restrict__ in) {
    size_t n4 = (size_t)ODIM * DDIM / 4;
    const float4* in4 = reinterpret_cast<const float4*>(in);
    for (size_t i = blockIdx.x * blockDim.x + threadIdx.x; i < n4;
         i += (size_t)gridDim.x * blockDim.x) {
        float4 v = in4[i];
        reinterpret_cast<__half2*>(g_wh)[i * 2]     = __floats2half2_rn(v.x, v.y);
        reinterpret_cast<__half2*>(g_wh)[i * 2 + 1] = __floats2half2_rn(v.z, v.w);
    }
}
// B_cat: g_we[o, l*16+r] = lora_b[l, o, r]; also zeroes g_cnt (runs before lists)
__global__ void conv_we(const float* __restrict__ lb) {
    const int i = blockIdx.x * blockDim.x + threadIdx.x;   // over ODIM*LMAX
    if (blockIdx.x == 0 && threadIdx.x < LMAX) g_cnt[threadIdx.x] = 0;
    if (i >= ODIM * LMAX) return;
    const int o = i >> 3;
    const int l = i & 7;
    const float4* src = reinterpret_cast<const float4*>(lb + ((size_t)l * ODIM + o) * RANK);
    __half2 h[8];
#pragma unroll
    for (int q = 0; q < 4; q++) {
        float4 v = src[q];
        h[q * 2]     = __floats2half2_rn(v.x, v.y);
        h[q * 2 + 1] = __floats2half2_rn(v.z, v.w);
    }
    __half2* dst = reinterpret_cast<__half2*>(g_we + (size_t)o * KEXT + l * RANK);
    *reinterpret_cast<uint4*>(dst)     = *reinterpret_cast<uint4*>(h);
    *reinterpret_cast<uint4*>(dst + 4) = *reinterpret_cast<uint4*>(h + 4);
}

__global__ void build_lists(const int* __restrict__ idx) {
    const int t = blockIdx.x * blockDim.x + threadIdx.x;
    if (t < T_TOK) {
        const int l = idx[t];
        const int p = atomicAdd(&g_cnt[l], 1);
        g_tok[l * T_TOK + p] = t;
    }
}

// ---------------------------------------------------------------------------
// Adapter-grouped LoRA shrink + x fp16 conversion fused.
// Block = (adapter l, group of 64 tokens). A_l chunk (fp32) staged in SMEM.
// Thread (ti, ds): token ti (0..63), d-slice ds (0..3): d = 16j + 4ds.
// Reads fp32 x once: accumulates s[t,:] AND emits g_xh[t,:] (fp16).
// ---------------------------------------------------------------------------
__global__ __launch_bounds__(256, 1)
void shrink_grouped(const float* __restrict__ x, const float* __restrict__ la) {
    const int l = blockIdx.x;
    const int start = blockIdx.y * 64;
    const int cnt = g_cnt[l];
    if (start >= cnt) return;
    const int tid = threadIdx.x;
    const int ti = tid >> 2;
    const int ds = tid & 3;

    __shared__ float Asm[RANK][512];
    __shared__ int toks[64];
    if (tid < 64)
        toks[tid] = (start + tid < cnt) ? g_tok[l * T_TOK + start + tid] : -1;
    __syncthreads();
    const int t = toks[ti];

    unsigned long long acc2[RANK];
#pragma unroll
    for (int r = 0; r < RANK; r++) acc2[r] = 0ull;

    for (int ch = 0; ch < DDIM / 512; ch++) {
        const float* Ab = la + (size_t)l * RANK * DDIM + ch * 512;
#pragma unroll
        for (int it = 0; it < 8; it++) {              // 2048 float4 loads
            const int i = it * 256 + tid;
            const int r = i >> 7;
            const int c4 = i & 127;
            reinterpret_cast<float4*>(&Asm[r][0])[c4] =
                reinterpret_cast<const float4*>(Ab + (size_t)r * DDIM)[c4];
        }
        __syncthreads();
        if (t >= 0) {
            const float* xr = x + (size_t)t * DDIM + ch * 512;
            __half* xh = g_xh + (size_t)t * DDIM + ch * 512;
#pragma unroll
            for (int j = 0; j < 32; j++) {
                const int d = j * 16 + ds * 4;
                float4 xv = *reinterpret_cast<const float4*>(xr + d);
                // emit fp16 copy (8 B store)
                __half2 h01 = __floats2half2_rn(xv.x, xv.y);
                __half2 h23 = __floats2half2_rn(xv.z, xv.w);
                uint2 pk;
                pk.x = *reinterpret_cast<uint32_t*>(&h01);
                pk.y = *reinterpret_cast<uint32_t*>(&h23);
                *reinterpret_cast<uint2*>(xh + d) = pk;
                // accumulate shrink
                const unsigned long long x01 = pack2(xv.x, xv.y);
                const unsigned long long x23 = pack2(xv.z, xv.w);
#pragma unroll
                for (int r = 0; r < RANK; r++) {
                    const unsigned long long* ap =
                        reinterpret_cast<const unsigned long long*>(&Asm[r][d]);
                    fma2(acc2[r], x01, ap[0]);
                    fma2(acc2[r], x23, ap[1]);
                }
            }
        }
        __syncthreads();
    }

    float acc[RANK];
#pragma unroll
    for (int r = 0; r < RANK; r++) {
        float2 v = unpack2(acc2[r]);
        acc[r] = v.x + v.y;
        acc[r] += __shfl_xor_sync(0xffffffffu, acc[r], 1);
        acc[r] += __shfl_xor_sync(0xffffffffu, acc[r], 2);
    }

    if (ds == 0 && t >= 0) {
        __half2* row = reinterpret_cast<__half2*>(g_xe + (size_t)t * KEXT);
        const int c0 = l * (RANK / 2);
#pragma unroll
        for (int c = 0; c < KEXT / 2; c++) {
            __half2 v = __floats2half2_rn(0.f, 0.f);
            if (c >= c0 && c < c0 + RANK / 2)
                v = __floats2half2_rn(acc[(c - c0) * 2], acc[(c - c0) * 2 + 1]);
            row[c] = v;
        }
    }
}

// ---------------------------------------------------------------------------
// Fused GEMM: out = [x | S~] @ [W | B_cat]^T   (fp16 mma.sync, fp32 accum)
// 128x256 CTA tile, BK=64, 4-stage cp.async pipeline (192 KB SMEM), 8 warps.
// Cross-chunk fragment prefetch: ldsm of next chunk's ks=0 issued right after
// the barrier, hidden under the cp.async issue burst.
// ---------------------------------------------------------------------------
#define BKC     64
#define NCHUNKC (KTOT / BKC)                  // 66
#define A_TILEB (128 * 128)
#define B_TILEB (256 * 128)
#define STAGEB  (A_TILEB + B_TILEB)           // 48 KB
#define STAGES  4
#define GEMM_SMEM (STAGES * STAGEB)           // 192 KB

__global__ __launch_bounds__(256, 1)
void gemm_mma(float* __restrict__ C) {
    extern __shared__ char smem[];
    const uint32_t sb = smem_u32(smem);
    const int tid  = threadIdx.x;
    const int wid  = tid >> 5;
    const int lane = tid & 31;

    const int bid = blockIdx.x;
    const int TN = ODIM / 256;                 // 16
    const int GRP = 8;
    const int per = GRP * TN;                  // 128
    const int m_t = (bid / per) * GRP + (bid % per) % GRP;
    const int n_t = (bid % per) / GRP;
    const int bm = m_t * 128;
    const int bn = n_t * 256;

    const int warp_m = wid & 1;
    const int warp_n = wid >> 1;

    auto issue_chunk = [&](int chunk, int stage) {
        const int k0 = chunk * BKC;
        const bool ext = (k0 >= DDIM);
        const __half* asrc = ext ? g_xe : g_xh;
        const __half* bsrc = ext ? g_we : g_wh;
        const size_t astr = ext ? KEXT : DDIM;
        const int ak = ext ? (k0 - DDIM) : k0;
        const uint32_t sbase = sb + (uint32_t)stage * STAGEB;
#pragma unroll
        for (int rep = 0; rep < 4; rep++) {            // A: 1024 cp16
            const int idx = rep * 256 + tid;
            const int r = idx >> 3;
            const int c = idx & 7;
            const void* g = asrc + (size_t)(bm + r) * astr + ak + c * 8;
            cp16(sbase + r * 128 + ((c ^ (r & 7)) << 4), g);
        }
#pragma unroll
        for (int rep = 0; rep < 8; rep++) {            // B: 2048 cp16
            const int idx = rep * 256 + tid;
            const int r = idx >> 3;
            const int c = idx & 7;
            const void* g = bsrc + (size_t)(bn + r) * astr + ak + c * 8;
            cp16(sbase + A_TILEB + r * 128 + ((c ^ (r & 7)) << 4), g);
        }
        asm volatile("cp.async.commit_group;" ::: "memory");
    };

    const int a_r = lane & 15;
    const int a_h = lane >> 4;
    const int b_r = (lane & 7) + ((lane >> 4) << 3);
    const int b_h = (lane >> 3) & 1;

    auto load_frags = [&](int stage, int ks, uint32_t (&af)[4][4], uint32_t (&bf)[4][4]) {
        const uint32_t Ab = sb + (uint32_t)stage * STAGEB;
        const uint32_t Bb = Ab + A_TILEB;
        const int cla = ks * 2 + a_h;
        const int clb = ks * 2 + b_h;
#pragma unroll
        for (int mt = 0; mt < 4; mt++) {
            const int row = warp_m * 64 + mt * 16 + a_r;
            ldsm4(af[mt], Ab + row * 128 + ((cla ^ (row & 7)) << 4));
        }
#pragma unroll
        for (int p = 0; p < 4; p++) {
            const int row = warp_n * 64 + p * 16 + b_r;
            ldsm4(bf[p], Bb + row * 128 + ((clb ^ (row & 7)) << 4));
        }
    };

    float acc[4][8][4];
#pragma unroll
    for (int i = 0; i < 4; i++)
#pragma unroll
        for (int j = 0; j < 8; j++)
#pragma unroll
            for (int q = 0; q < 4; q++) acc[i][j][q] = 0.f;

#pragma unroll
    for (int s = 0; s < STAGES - 1; s++) issue_chunk(s, s);

    uint32_t af[2][4][4], bf[2][4][4];
    asm volatile("cp.async.wait_group %0;" :: "n"(STAGES - 2) : "memory");
    __syncthreads();
    load_frags(0, 0, af[0], bf[0]);

    for (int i = 0; i < NCHUNKC; i++) {
        const int stage = i & (STAGES - 1);
#pragma unroll
        for (int ks = 0; ks < 4; ks++) {
            const int cur = ks & 1;
            if (ks < 3) load_frags(stage, ks + 1, af[cur ^ 1], bf[cur ^ 1]);
#pragma unroll
            for (int mt = 0; mt < 4; mt++)
#pragma unroll
                for (int nt = 0; nt < 8; nt++)
                    mma_fp16(acc[mt][nt], af[cur][mt],
                             bf[cur][nt >> 1][(nt & 1) * 2],
                             bf[cur][nt >> 1][(nt & 1) * 2 + 1]);
        }
        if (i + 1 < NCHUNKC) {
            // Groups complete in commit order: allowing 1 outstanding (chunk
            // i+2) guarantees chunk i+1's stage is resident.
            asm volatile("cp.async.wait_group 1;" ::: "memory");
            __syncthreads();
            load_frags((i + 1) & (STAGES - 1), 0, af[0], bf[0]);
            if (i + STAGES - 1 < NCHUNKC)
                issue_chunk(i + STAGES - 1, (i + STAGES - 1) & (STAGES - 1));
        }
    }

    const int er = lane >> 2;
    const int ec = (lane & 3) * 2;
#pragma unroll
    for (int mt = 0; mt < 4; mt++) {
#pragma unroll
        for (int nt = 0; nt < 8; nt++) {
            float* base = C + (size_t)(bm + warp_m * 64 + mt * 16 + er) * ODIM +
                          bn + warp_n * 64 + nt * 8 + ec;
            *reinterpret_cast<float2*>(base) =
                make_float2(acc[mt][nt][0], acc[mt][nt][1]);
            *reinterpret_cast<float2*>(base + 8 * ODIM) =
                make_float2(acc[mt][nt][2], acc[mt][nt][3]);
        }
    }
}

// ---------------------------------------------------------------------------
// Launch: inputs order: x, weight, lora_a, lora_b, token_lora_idx
// ---------------------------------------------------------------------------
extern "C" void kernel_launch(void* const* d_in, const int* in_sizes, int n_in,
                              void* d_out, int out_size) {
    const float* x   = (const float*)d_in[0];
    const float* w   = (const float*)d_in[1];
    const float* la  = (const float*)d_in[2];
    const float* lb  = (const float*)d_in[3];
    const int*   idx = (const int*)d_in[4];
    float* out = (float*)d_out;

    cudaFuncSetAttribute(gemm_mma, cudaFuncAttributeMaxDynamicSharedMemorySize,
                         GEMM_SMEM);

    conv_w<<<1024, 256>>>(w);
    conv_we<<<(ODIM * LMAX + 255) / 256, 256>>>(lb);    // also zeroes g_cnt
    build_lists<<<T_TOK / 256, 256>>>(idx);
    shrink_grouped<<<dim3(LMAX, T_TOK / 64), 256>>>(x, la);   // also writes g_xh
    gemm_mma<<<(T_TOK / 128) * (ODIM / 256), 256, GEMM_SMEM>>>(out);
}